// round 1
// baseline (speedup 1.0000x reference)
#include <cuda_runtime.h>
#include <math.h>

namespace {
constexpr int N       = 256;
constexpr int NSTEPS  = 32;
constexpr int NIMG    = 384;   // 128 batch * 3 channels
constexpr int BM = 64, BN = 64, BK = 16;
}

// Scratch (allocation-free rule: __device__ globals)
__device__ float g_D[N * N];                 // DCT-II orthonormal matrix
__device__ float g_E[NSTEPS * N];            // per-step 1D frequency decay
__device__ float g_M[NSTEPS * N * N];        // M_s = D * diag(e_s) * D
__device__ float g_T[NIMG * N * N];          // intermediate T = M * X  (100 MB)

// Build D and E. Exact range reduction: cos(pi*(n+0.5)*k/N) = cos(pi*p/(2N)),
// p = (2n+1)*k mod 4N. fp64 cos on the reduced argument.
__global__ void k_init(const float* __restrict__ sigmas) {
    int k = blockIdx.x;     // 0..255 (frequency row)
    int n = threadIdx.x;    // 0..255 (spatial col)
    int p = ((2 * n + 1) * k) & (4 * N - 1);
    double v = sqrt(2.0 / (double)N) * cos(M_PI * (double)p / (double)(2 * N));
    if (k == 0) v *= 0.7071067811865476;
    g_D[k * N + n] = (float)v;

    if (k < NSTEPS) {
        float sig = sigmas[k];
        float t   = 0.5f * sig * sig;
        float f   = (float)M_PI * (float)n / (float)N;
        g_E[k * N + n] = expf(-f * f * t);
    }
}

// One tiled fp32 GEMM, 64x64x16 block tile, 256 threads, 4x4 per thread.
// MODE 0: C(g_M[z]) = (g_D col-scaled by g_E[z]) * g_D          z in [0,32)
// MODE 1: C(g_T[z]) = g_M[step] * X[z]            (NN)          z in [0,384)
// MODE 2: C(out[z]) = g_T[z]    * g_M[step]^T     (NT)          z in [0,384)
template <int MODE>
__global__ __launch_bounds__(256) void k_gemm(const float* __restrict__ X,
                                              float* __restrict__ Out,
                                              const int* __restrict__ fwd_steps) {
    __shared__ float As[BK][BM + 4];
    __shared__ float Bs[BK][BN + 4];

    const int z = blockIdx.z;
    const float* A;
    const float* B;
    float* C;
    const float* e = nullptr;

    if (MODE == 0) {
        A = g_D;
        B = g_D;
        C = g_M + (size_t)z * N * N;
        e = g_E + z * N;
    } else {
        const int step = fwd_steps[z / 3];           // image z = b*3 + c
        if (MODE == 1) {
            A = g_M + (size_t)step * N * N;
            B = X   + (size_t)z * N * N;
            C = g_T + (size_t)z * N * N;
        } else {
            A = g_T + (size_t)z * N * N;
            B = g_M + (size_t)step * N * N;          // used transposed
            C = Out + (size_t)z * N * N;
        }
    }

    const int m0 = blockIdx.y * BM;
    const int n0 = blockIdx.x * BN;
    const int tid = threadIdx.x;
    const int ty = tid >> 4;        // 0..15
    const int tx = tid & 15;        // 0..15

    // Loader indices
    const int ar = tid >> 2;        // 0..63  (row within 64-row tile)
    const int ac = tid & 3;         // 0..3   (float4 along K)
    const int br = tid >> 4;        // 0..15  (K row, NN B loader)
    const int bc = tid & 15;        // 0..15  (float4 along N)

    float acc[4][4] = {};

    for (int k0 = 0; k0 < N; k0 += BK) {
        // A tile: 64 rows x 16 K, transpose into As[k][m]
        float4 a = *(const float4*)&A[(size_t)(m0 + ar) * N + k0 + ac * 4];
        if (MODE == 0) {
            a.x *= e[k0 + ac * 4 + 0];
            a.y *= e[k0 + ac * 4 + 1];
            a.z *= e[k0 + ac * 4 + 2];
            a.w *= e[k0 + ac * 4 + 3];
        }
        As[ac * 4 + 0][ar] = a.x;
        As[ac * 4 + 1][ar] = a.y;
        As[ac * 4 + 2][ar] = a.z;
        As[ac * 4 + 3][ar] = a.w;

        if (MODE == 2) {
            // B used as B^T: load 64 rows (n) x 16 K of the row-major matrix,
            // transpose into Bs[k][n]
            float4 b = *(const float4*)&B[(size_t)(n0 + ar) * N + k0 + ac * 4];
            Bs[ac * 4 + 0][ar] = b.x;
            Bs[ac * 4 + 1][ar] = b.y;
            Bs[ac * 4 + 2][ar] = b.z;
            Bs[ac * 4 + 3][ar] = b.w;
        } else {
            // NN: B tile is 16 K-rows x 64 N, already [k][n]
            float4 b = *(const float4*)&B[(size_t)(k0 + br) * N + n0 + bc * 4];
            *(float4*)&Bs[br][bc * 4] = b;
        }
        __syncthreads();

#pragma unroll
        for (int kk = 0; kk < BK; kk++) {
            float4 av = *(const float4*)&As[kk][ty * 4];
            float4 bv = *(const float4*)&Bs[kk][tx * 4];
            float am[4] = {av.x, av.y, av.z, av.w};
            float bm[4] = {bv.x, bv.y, bv.z, bv.w};
#pragma unroll
            for (int i = 0; i < 4; i++)
#pragma unroll
                for (int j = 0; j < 4; j++)
                    acc[i][j] = fmaf(am[i], bm[j], acc[i][j]);
        }
        __syncthreads();
    }

#pragma unroll
    for (int i = 0; i < 4; i++) {
        float4 c = make_float4(acc[i][0], acc[i][1], acc[i][2], acc[i][3]);
        *(float4*)&C[(size_t)(m0 + ty * 4 + i) * N + n0 + tx * 4] = c;
    }
}

extern "C" void kernel_launch(void* const* d_in, const int* in_sizes, int n_in,
                              void* d_out, int out_size) {
    // Identify inputs by size (robust to ordering): x=25165824, sigmas=32, steps=128
    const float* x      = nullptr;
    const float* sigmas = nullptr;
    const int*   steps  = nullptr;
    for (int i = 0; i < n_in; i++) {
        if (in_sizes[i] == NSTEPS)            sigmas = (const float*)d_in[i];
        else if (in_sizes[i] == 128)          steps  = (const int*)d_in[i];
        else                                  x      = (const float*)d_in[i];
    }
    float* out = (float*)d_out;

    k_init<<<N, N>>>(sigmas);

    dim3 gM(N / BN, N / BM, NSTEPS);
    k_gemm<0><<<gM, 256>>>(nullptr, nullptr, nullptr);

    dim3 gI(N / BN, N / BM, NIMG);
    k_gemm<1><<<gI, 256>>>(x, nullptr, steps);
    k_gemm<2><<<gI, 256>>>(nullptr, out, steps);
}

// round 2
// speedup vs baseline: 1.3558x; 1.3558x over previous
#include <cuda_runtime.h>
#include <math.h>

namespace {
constexpr int N      = 256;
constexpr int NSTEPS = 32;
constexpr int NIMG   = 384;   // 128 batch * 3 channels
constexpr int BM = 128, BN = 128, BK = 16;
constexpr int LDSW = BM + 4;  // smem row stride
}

// Scratch (allocation-free rule: __device__ globals)
__device__ float g_D[N * N];                 // DCT-II orthonormal matrix
__device__ float g_E[NSTEPS * N];            // per-step 1D frequency decay
__device__ float g_M[NSTEPS * N * N];        // M_s = D * diag(e_s) * D
__device__ float g_T[NIMG * N * N];          // intermediate T = M * X

// Build D and E. Exact range reduction: cos(pi*(n+0.5)*k/N) = cos(pi*p/(2N)),
// p = (2n+1)*k mod 4N, fp64 cos on the reduced argument.
__global__ void k_init(const float* __restrict__ sigmas) {
    int k = blockIdx.x;
    int n = threadIdx.x;
    int p = ((2 * n + 1) * k) & (4 * N - 1);
    double v = sqrt(2.0 / (double)N) * cos(M_PI * (double)p / (double)(2 * N));
    if (k == 0) v *= 0.7071067811865476;
    g_D[k * N + n] = (float)v;

    if (k < NSTEPS) {
        float sig = sigmas[k];
        float t   = 0.5f * sig * sig;
        float f   = (float)M_PI * (float)n / (float)N;
        g_E[k * N + n] = expf(-f * f * t);
    }
}

typedef unsigned long long u64;

__device__ __forceinline__ u64 pack2(float x, float y) {
    u64 r;
    asm("mov.b64 %0, {%1, %2};" : "=l"(r) : "f"(x), "f"(y));
    return r;
}
__device__ __forceinline__ void unpack2(u64 v, float& x, float& y) {
    asm("mov.b64 {%0, %1}, %2;" : "=f"(x), "=f"(y) : "l"(v));
}
// Packed fp32x2 FMA: d = a*b + d on both 32-bit lanes. Full-rate fp32 path
// on sm_103a (3-reg scalar FFMA is half-rate).
__device__ __forceinline__ void ffma2(u64& d, u64 a, u64 b) {
    asm("fma.rn.f32x2 %0, %1, %2, %0;" : "+l"(d) : "l"(a), "l"(b));
}

// 128x128x16 block tile, 256 threads, 8x8 per thread (2x2 spread of 4x4),
// packed f32x2 FMA.
// MODE 0: g_M[z]  = (g_D col-scaled by g_E[z]) * g_D            z in [0,32)
// MODE 1: g_T[z]  = g_M[step] * X[z]             (NN)           z in [0,384)
// MODE 2: out[z]  = g_T[z]    * g_M[step]^T      (NT)           z in [0,384)
template <int MODE>
__global__ __launch_bounds__(256, 2) void k_gemm(const float* __restrict__ X,
                                                 float* __restrict__ Out,
                                                 const int* __restrict__ fwd_steps) {
    __shared__ float As[BK][LDSW];
    __shared__ float Bs[BK][LDSW];

    const int z = blockIdx.z;
    const float* A;
    const float* B;
    float* C;
    const float* e = nullptr;

    if (MODE == 0) {
        A = g_D;
        B = g_D;
        C = g_M + (size_t)z * N * N;
        e = g_E + z * N;
    } else {
        const int step = fwd_steps[z / 3];
        if (MODE == 1) {
            A = g_M + (size_t)step * N * N;
            B = X   + (size_t)z * N * N;
            C = g_T + (size_t)z * N * N;
        } else {
            A = g_T + (size_t)z * N * N;
            B = g_M + (size_t)step * N * N;   // used transposed
            C = Out + (size_t)z * N * N;
        }
    }

    const int m0  = blockIdx.y * BM;
    const int n0  = blockIdx.x * BN;
    const int tid = threadIdx.x;
    const int ty  = tid >> 4;           // 0..15
    const int tx  = tid & 15;           // 0..15

    // A-style loader (also B for MODE 2): each thread loads 32B of one row
    const int lr = (tid * 2) >> 2;      // row within 128-row slab
    const int lc = (tid * 2) & 3;       // chunk: 0 or 2 (pairs {0,1},{2,3})
    // B NN loader
    const int bkr = (tid * 2) >> 5;     // K row 0..15
    const int bnc = (tid * 2) & 31;     // float4 chunk along N (even)

    u64 acc[8][4];
#pragma unroll
    for (int i = 0; i < 8; i++)
#pragma unroll
        for (int jp = 0; jp < 4; jp++) acc[i][jp] = 0ull;

    // prefetch tile k0 = 0
    float4 pa0 = *(const float4*)&A[(size_t)(m0 + lr) * N + lc * 4];
    float4 pa1 = *(const float4*)&A[(size_t)(m0 + lr) * N + lc * 4 + 4];
    float4 pb0, pb1;
    if (MODE == 2) {
        pb0 = *(const float4*)&B[(size_t)(n0 + lr) * N + lc * 4];
        pb1 = *(const float4*)&B[(size_t)(n0 + lr) * N + lc * 4 + 4];
    } else {
        pb0 = *(const float4*)&B[(size_t)bkr * N + n0 + bnc * 4];
        pb1 = *(const float4*)&B[(size_t)bkr * N + n0 + bnc * 4 + 4];
    }

    for (int k0 = 0; k0 < N; k0 += BK) {
        if (MODE == 0) {
            pa0.x *= e[k0 + lc * 4 + 0];
            pa0.y *= e[k0 + lc * 4 + 1];
            pa0.z *= e[k0 + lc * 4 + 2];
            pa0.w *= e[k0 + lc * 4 + 3];
            pa1.x *= e[k0 + lc * 4 + 4];
            pa1.y *= e[k0 + lc * 4 + 5];
            pa1.z *= e[k0 + lc * 4 + 6];
            pa1.w *= e[k0 + lc * 4 + 7];
        }
        __syncthreads();
        // A transpose into As[k][m]
        As[lc * 4 + 0][lr] = pa0.x;
        As[lc * 4 + 1][lr] = pa0.y;
        As[lc * 4 + 2][lr] = pa0.z;
        As[lc * 4 + 3][lr] = pa0.w;
        As[lc * 4 + 4][lr] = pa1.x;
        As[lc * 4 + 5][lr] = pa1.y;
        As[lc * 4 + 6][lr] = pa1.z;
        As[lc * 4 + 7][lr] = pa1.w;
        if (MODE == 2) {
            Bs[lc * 4 + 0][lr] = pb0.x;
            Bs[lc * 4 + 1][lr] = pb0.y;
            Bs[lc * 4 + 2][lr] = pb0.z;
            Bs[lc * 4 + 3][lr] = pb0.w;
            Bs[lc * 4 + 4][lr] = pb1.x;
            Bs[lc * 4 + 5][lr] = pb1.y;
            Bs[lc * 4 + 6][lr] = pb1.z;
            Bs[lc * 4 + 7][lr] = pb1.w;
        } else {
            *(float4*)&Bs[bkr][bnc * 4]     = pb0;
            *(float4*)&Bs[bkr][bnc * 4 + 4] = pb1;
        }
        __syncthreads();

        // prefetch next tile while computing this one
        if (k0 + BK < N) {
            pa0 = *(const float4*)&A[(size_t)(m0 + lr) * N + k0 + BK + lc * 4];
            pa1 = *(const float4*)&A[(size_t)(m0 + lr) * N + k0 + BK + lc * 4 + 4];
            if (MODE == 2) {
                pb0 = *(const float4*)&B[(size_t)(n0 + lr) * N + k0 + BK + lc * 4];
                pb1 = *(const float4*)&B[(size_t)(n0 + lr) * N + k0 + BK + lc * 4 + 4];
            } else {
                pb0 = *(const float4*)&B[(size_t)(k0 + BK + bkr) * N + n0 + bnc * 4];
                pb1 = *(const float4*)&B[(size_t)(k0 + BK + bkr) * N + n0 + bnc * 4 + 4];
            }
        }

#pragma unroll
        for (int kk = 0; kk < BK; kk++) {
            float4 av0 = *(const float4*)&As[kk][ty * 4];
            float4 av1 = *(const float4*)&As[kk][64 + ty * 4];
            float4 bv0 = *(const float4*)&Bs[kk][tx * 4];
            float4 bv1 = *(const float4*)&Bs[kk][64 + tx * 4];
            u64 a2[8];
            a2[0] = pack2(av0.x, av0.x);
            a2[1] = pack2(av0.y, av0.y);
            a2[2] = pack2(av0.z, av0.z);
            a2[3] = pack2(av0.w, av0.w);
            a2[4] = pack2(av1.x, av1.x);
            a2[5] = pack2(av1.y, av1.y);
            a2[6] = pack2(av1.z, av1.z);
            a2[7] = pack2(av1.w, av1.w);
            u64 b2[4];
            b2[0] = pack2(bv0.x, bv0.y);
            b2[1] = pack2(bv0.z, bv0.w);
            b2[2] = pack2(bv1.x, bv1.y);
            b2[3] = pack2(bv1.z, bv1.w);
#pragma unroll
            for (int i = 0; i < 8; i++)
#pragma unroll
                for (int jp = 0; jp < 4; jp++) ffma2(acc[i][jp], a2[i], b2[jp]);
        }
    }

    // epilogue: 2x2 spread of 4x4 tiles
#pragma unroll
    for (int i = 0; i < 8; i++) {
        const int row = m0 + ((i < 4) ? (ty * 4 + i) : (64 + ty * 4 + (i - 4)));
        float4 c0, c1;
        unpack2(acc[i][0], c0.x, c0.y);
        unpack2(acc[i][1], c0.z, c0.w);
        unpack2(acc[i][2], c1.x, c1.y);
        unpack2(acc[i][3], c1.z, c1.w);
        *(float4*)&C[(size_t)row * N + n0 + tx * 4]      = c0;
        *(float4*)&C[(size_t)row * N + n0 + 64 + tx * 4] = c1;
    }
}

extern "C" void kernel_launch(void* const* d_in, const int* in_sizes, int n_in,
                              void* d_out, int out_size) {
    const float* x      = nullptr;
    const float* sigmas = nullptr;
    const int*   steps  = nullptr;
    for (int i = 0; i < n_in; i++) {
        if (in_sizes[i] == NSTEPS)   sigmas = (const float*)d_in[i];
        else if (in_sizes[i] == 128) steps  = (const int*)d_in[i];
        else                         x      = (const float*)d_in[i];
    }
    float* out = (float*)d_out;

    k_init<<<N, N>>>(sigmas);

    dim3 gM(N / BN, N / BM, NSTEPS);
    k_gemm<0><<<gM, 256>>>(nullptr, nullptr, nullptr);

    dim3 gI(N / BN, N / BM, NIMG);
    k_gemm<1><<<gI, 256>>>(x, nullptr, steps);
    k_gemm<2><<<gI, 256>>>(nullptr, out, steps);
}

// round 4
// speedup vs baseline: 1.6360x; 1.2067x over previous
#include <cuda_runtime.h>
#include <cuda_bf16.h>
#include <math.h>
#include <stdint.h>

namespace {
constexpr int N      = 256;
constexpr int NSTEPS = 32;
constexpr int NIMG   = 384;                  // 128 batch * 3 channels

// fp32 M-builder tile
constexpr int BM = 128, BN = 128, BK = 16;
constexpr int LDSW = BM + 4;

// fused kernel smem layout (bytes). Strides in elements (bf16).
constexpr int T_STR = 264;                   // 128x264 T buffers (hi/lo)
constexpr int X_STR = 264;                   // 32x264 X chunk buffers
constexpr int A_STR = 40;                    // M tile buffers
constexpr int SZ_T  = 128 * T_STR * 2;       // 67584
constexpr int OFF_TH = 0;
constexpr int OFF_TL = SZ_T;
constexpr int OFF_P  = 2 * SZ_T;             // 135168
constexpr int SZ_A   = 128 * A_STR * 2;      // 10240
constexpr int OFF_AH = OFF_P;
constexpr int OFF_AL = OFF_AH + SZ_A;
constexpr int SZ_X   = 32 * X_STR * 2;       // 16896
constexpr int OFF_XH = OFF_AL + SZ_A;
constexpr int OFF_XL = OFF_XH + SZ_X;
constexpr int SZ_B   = 256 * A_STR * 2;      // 20480 (pass2 M rows, reuses OFF_P region)
constexpr int OFF_BH = OFF_P;
constexpr int OFF_BL = OFF_BH + SZ_B;
constexpr int SMEM_FUSED = OFF_XL + SZ_X;    // 189440
}

// ---------------- device globals (allocation-free scratch) ----------------
__device__ float g_D[N * N];
__device__ float g_E[NSTEPS * N];
__device__ float g_M[NSTEPS * N * N];                     // fp32 M_s
__device__ __align__(16) __nv_bfloat16 g_Mh[NSTEPS * N * N];
__device__ __align__(16) __nv_bfloat16 g_Ml[NSTEPS * N * N];

// ---------------- helpers ----------------
__device__ __forceinline__ uint32_t smem_u32(const void* p) {
    uint32_t a;
    asm("{ .reg .u64 t; cvta.to.shared.u64 t, %1; cvt.u32.u64 %0, t; }" : "=r"(a) : "l"(p));
    return a;
}
__device__ __forceinline__ void ldsm4(uint32_t* r, uint32_t a) {
    asm volatile("ldmatrix.sync.aligned.m8n8.x4.shared.b16 {%0,%1,%2,%3}, [%4];"
                 : "=r"(r[0]), "=r"(r[1]), "=r"(r[2]), "=r"(r[3]) : "r"(a));
}
__device__ __forceinline__ void ldsm4t(uint32_t* r, uint32_t a) {
    asm volatile("ldmatrix.sync.aligned.m8n8.x4.trans.shared.b16 {%0,%1,%2,%3}, [%4];"
                 : "=r"(r[0]), "=r"(r[1]), "=r"(r[2]), "=r"(r[3]) : "r"(a));
}
__device__ __forceinline__ void mma_bf16(float* d, const uint32_t* a, uint32_t b0, uint32_t b1) {
    asm volatile(
        "mma.sync.aligned.m16n8k16.row.col.f32.bf16.bf16.f32 "
        "{%0,%1,%2,%3}, {%4,%5,%6,%7}, {%8,%9}, {%0,%1,%2,%3};"
        : "+f"(d[0]), "+f"(d[1]), "+f"(d[2]), "+f"(d[3])
        : "r"(a[0]), "r"(a[1]), "r"(a[2]), "r"(a[3]), "r"(b0), "r"(b1));
}
__device__ __forceinline__ uint32_t pkbf2(float a, float b) {
    __nv_bfloat162 t = __floats2bfloat162_rn(a, b);
    return reinterpret_cast<uint32_t&>(t);
}
__device__ __forceinline__ void split8(const float* v, uint4& H, uint4& L) {
    float h[8], l[8];
#pragma unroll
    for (int i = 0; i < 8; i++) {
        __nv_bfloat16 b = __float2bfloat16_rn(v[i]);
        h[i] = __bfloat162float(b);
        l[i] = v[i] - h[i];
    }
    H = make_uint4(pkbf2(h[0], h[1]), pkbf2(h[2], h[3]), pkbf2(h[4], h[5]), pkbf2(h[6], h[7]));
    L = make_uint4(pkbf2(l[0], l[1]), pkbf2(l[2], l[3]), pkbf2(l[4], l[5]), pkbf2(l[6], l[7]));
}

// ---------------- init: D and E ----------------
__global__ void k_init(const float* __restrict__ sigmas) {
    int k = blockIdx.x, n = threadIdx.x;
    int p = ((2 * n + 1) * k) & (4 * N - 1);
    double v = sqrt(2.0 / (double)N) * cos(M_PI * (double)p / (double)(2 * N));
    if (k == 0) v *= 0.7071067811865476;
    g_D[k * N + n] = (float)v;
    if (k < NSTEPS) {
        float sig = sigmas[k];
        float t = 0.5f * sig * sig;
        float f = (float)M_PI * (float)n / (float)N;
        g_E[k * N + n] = expf(-f * f * t);
    }
}

// ---------------- fp32 builder: M_s = (D diag(e)) D ----------------
typedef unsigned long long u64;
__device__ __forceinline__ u64 pack2(float x, float y) {
    u64 r; asm("mov.b64 %0, {%1, %2};" : "=l"(r) : "f"(x), "f"(y)); return r;
}
__device__ __forceinline__ void unpack2(u64 v, float& x, float& y) {
    asm("mov.b64 {%0, %1}, %2;" : "=f"(x), "=f"(y) : "l"(v));
}
__device__ __forceinline__ void ffma2(u64& d, u64 a, u64 b) {
    asm("fma.rn.f32x2 %0, %1, %2, %0;" : "+l"(d) : "l"(a), "l"(b));
}

__global__ __launch_bounds__(256, 2) void k_gemm0() {
    __shared__ float As[BK][LDSW];
    __shared__ float Bs[BK][LDSW];
    const int z = blockIdx.z;
    const float* A = g_D;
    const float* B = g_D;
    float* C = g_M + (size_t)z * N * N;
    const float* e = g_E + z * N;

    const int m0 = blockIdx.y * BM, n0 = blockIdx.x * BN;
    const int tid = threadIdx.x;
    const int ty = tid >> 4, tx = tid & 15;
    const int lr = (tid * 2) >> 2, lc = (tid * 2) & 3;
    const int bkr = (tid * 2) >> 5, bnc = (tid * 2) & 31;

    u64 acc[8][4];
#pragma unroll
    for (int i = 0; i < 8; i++)
#pragma unroll
        for (int j = 0; j < 4; j++) acc[i][j] = 0ull;

    for (int k0 = 0; k0 < N; k0 += BK) {
        float4 a0 = *(const float4*)&A[(size_t)(m0 + lr) * N + k0 + lc * 4];
        float4 a1 = *(const float4*)&A[(size_t)(m0 + lr) * N + k0 + lc * 4 + 4];
        a0.x *= e[k0 + lc * 4 + 0]; a0.y *= e[k0 + lc * 4 + 1];
        a0.z *= e[k0 + lc * 4 + 2]; a0.w *= e[k0 + lc * 4 + 3];
        a1.x *= e[k0 + lc * 4 + 4]; a1.y *= e[k0 + lc * 4 + 5];
        a1.z *= e[k0 + lc * 4 + 6]; a1.w *= e[k0 + lc * 4 + 7];
        float4 b0 = *(const float4*)&B[(size_t)(k0 + bkr) * N + n0 + bnc * 4];
        float4 b1 = *(const float4*)&B[(size_t)(k0 + bkr) * N + n0 + bnc * 4 + 4];
        __syncthreads();
        As[lc * 4 + 0][lr] = a0.x; As[lc * 4 + 1][lr] = a0.y;
        As[lc * 4 + 2][lr] = a0.z; As[lc * 4 + 3][lr] = a0.w;
        As[lc * 4 + 4][lr] = a1.x; As[lc * 4 + 5][lr] = a1.y;
        As[lc * 4 + 6][lr] = a1.z; As[lc * 4 + 7][lr] = a1.w;
        *(float4*)&Bs[bkr][bnc * 4]     = b0;
        *(float4*)&Bs[bkr][bnc * 4 + 4] = b1;
        __syncthreads();
#pragma unroll
        for (int kk = 0; kk < BK; kk++) {
            float4 av0 = *(const float4*)&As[kk][ty * 4];
            float4 av1 = *(const float4*)&As[kk][64 + ty * 4];
            float4 bv0 = *(const float4*)&Bs[kk][tx * 4];
            float4 bv1 = *(const float4*)&Bs[kk][64 + tx * 4];
            u64 a2[8] = {pack2(av0.x, av0.x), pack2(av0.y, av0.y), pack2(av0.z, av0.z),
                         pack2(av0.w, av0.w), pack2(av1.x, av1.x), pack2(av1.y, av1.y),
                         pack2(av1.z, av1.z), pack2(av1.w, av1.w)};
            u64 b2[4] = {pack2(bv0.x, bv0.y), pack2(bv0.z, bv0.w),
                         pack2(bv1.x, bv1.y), pack2(bv1.z, bv1.w)};
#pragma unroll
            for (int i = 0; i < 8; i++)
#pragma unroll
                for (int j = 0; j < 4; j++) ffma2(acc[i][j], a2[i], b2[j]);
        }
    }
#pragma unroll
    for (int i = 0; i < 8; i++) {
        const int row = m0 + ((i < 4) ? (ty * 4 + i) : (64 + ty * 4 + (i - 4)));
        float4 c0, c1;
        unpack2(acc[i][0], c0.x, c0.y); unpack2(acc[i][1], c0.z, c0.w);
        unpack2(acc[i][2], c1.x, c1.y); unpack2(acc[i][3], c1.z, c1.w);
        *(float4*)&C[(size_t)row * N + n0 + tx * 4]      = c0;
        *(float4*)&C[(size_t)row * N + n0 + 64 + tx * 4] = c1;
    }
}

// ---------------- split M into row-major bf16 hi/lo ----------------
__global__ void k_split_M() {
    const int s = blockIdx.x;
    const float* src = g_M + (size_t)s * N * N;
    __nv_bfloat16* dh = g_Mh + (size_t)s * N * N;
    __nv_bfloat16* dl = g_Ml + (size_t)s * N * N;
#pragma unroll 1
    for (int it = 0; it < 32; it++) {
        int base = it * 2048 + threadIdx.x * 8;
        float4 v0 = *(const float4*)&src[base];
        float4 v1 = *(const float4*)&src[base + 4];
        float v[8] = {v0.x, v0.y, v0.z, v0.w, v1.x, v1.y, v1.z, v1.w};
        uint4 H, L; split8(v, H, L);
        *(uint4*)&dh[base] = H;
        *(uint4*)&dl[base] = L;
    }
}

// ---------------- fused tensor kernel: out[h-half] = (M X) M^T ----------------
// grid (NIMG, 2); 256 threads; warp grid 2(m) x 4(n); warp tile 64x64.
__global__ __launch_bounds__(256, 1) void k_fused(const float* __restrict__ X,
                                                  float* __restrict__ Out,
                                                  const int* __restrict__ steps) {
    extern __shared__ char sm[];
    const int z = blockIdx.x, h = blockIdx.y;
    const int s = steps[z / 3];
    const int t = threadIdx.x, lane = t & 31, wid = t >> 5;
    const int wm = wid >> 2, wn = wid & 3;
    const uint32_t sb = smem_u32(sm);
    const int lr = lane & 15, lc8 = (lane >> 4) * 8;

    const __nv_bfloat16* Mh = g_Mh + (size_t)s * N * N;
    const __nv_bfloat16* Ml = g_Ml + (size_t)s * N * N;

    float acc[4][8][4];
#pragma unroll
    for (int a = 0; a < 4; a++)
#pragma unroll
        for (int b = 0; b < 8; b++)
#pragma unroll
            for (int c = 0; c < 4; c++) acc[a][b][c] = 0.0f;

    // ---------------- pass 1: T = M[h rows] * X ----------------
#pragma unroll 1
    for (int kc = 0; kc < 8; kc++) {
        {   // A tile: M rows [h*128, h*128+128), cols [kc*32, +32)
            int r = t >> 1, q = t & 1;
            size_t go = (size_t)(h * 128 + r) * N + kc * 32 + q * 16;
            const uint4* ph = (const uint4*)(Mh + go);
            const uint4* pl = (const uint4*)(Ml + go);
            uint4 h0 = ph[0], h1 = ph[1], l0 = pl[0], l1 = pl[1];
            char* dh = sm + OFF_AH + ((size_t)r * A_STR + q * 16) * 2;
            char* dl = sm + OFF_AL + ((size_t)r * A_STR + q * 16) * 2;
            *(uint4*)dh = h0; *(uint4*)(dh + 16) = h1;
            *(uint4*)dl = l0; *(uint4*)(dl + 16) = l1;
        }
        {   // X chunk: rows [kc*32, +32) x 256 cols, fp32 -> split bf16
            int xr = t >> 3, xc = (t & 7) * 32;
            const float4* xs = (const float4*)(X + (size_t)z * N * N +
                                               (size_t)(kc * 32 + xr) * N + xc);
#pragma unroll
            for (int i = 0; i < 8; i++) {
                float4 v = xs[i];
                float vv[4] = {v.x, v.y, v.z, v.w};
                float hh[4], ll[4];
#pragma unroll
                for (int u = 0; u < 4; u++) {
                    __nv_bfloat16 b = __float2bfloat16_rn(vv[u]);
                    hh[u] = __bfloat162float(b);
                    ll[u] = vv[u] - hh[u];
                }
                uint2 H = make_uint2(pkbf2(hh[0], hh[1]), pkbf2(hh[2], hh[3]));
                uint2 L = make_uint2(pkbf2(ll[0], ll[1]), pkbf2(ll[2], ll[3]));
                size_t so = ((size_t)xr * X_STR + xc + i * 4) * 2;
                *(uint2*)(sm + OFF_XH + so) = H;
                *(uint2*)(sm + OFF_XL + so) = L;
            }
        }
        __syncthreads();
#pragma unroll
        for (int ks = 0; ks < 2; ks++) {
            uint32_t Ah[4][4], Al[4][4], Bh[4][4], Bl[4][4];
#pragma unroll
            for (int mi = 0; mi < 4; mi++) {
                uint32_t a = sb + OFF_AH + ((wm * 64 + mi * 16 + lr) * A_STR + ks * 16 + lc8) * 2;
                ldsm4(Ah[mi], a);
                ldsm4(Al[mi], a + SZ_A);
            }
#pragma unroll
            for (int nj = 0; nj < 4; nj++) {
                uint32_t a = sb + OFF_XH + ((ks * 16 + lr) * X_STR + wn * 64 + nj * 16 + lc8) * 2;
                ldsm4t(Bh[nj], a);
                ldsm4t(Bl[nj], a + SZ_X);
            }
#pragma unroll
            for (int mi = 0; mi < 4; mi++)
#pragma unroll
                for (int nj = 0; nj < 4; nj++) {
                    mma_bf16(acc[mi][nj * 2],     Ah[mi], Bh[nj][0], Bh[nj][1]);
                    mma_bf16(acc[mi][nj * 2 + 1], Ah[mi], Bh[nj][2], Bh[nj][3]);
                    mma_bf16(acc[mi][nj * 2],     Ah[mi], Bl[nj][0], Bl[nj][1]);
                    mma_bf16(acc[mi][nj * 2 + 1], Ah[mi], Bl[nj][2], Bl[nj][3]);
                    mma_bf16(acc[mi][nj * 2],     Al[mi], Bh[nj][0], Bh[nj][1]);
                    mma_bf16(acc[mi][nj * 2 + 1], Al[mi], Bh[nj][2], Bh[nj][3]);
                }
        }
        __syncthreads();
    }

    // park T (bf16 hi/lo) in smem, zero accumulators
#pragma unroll
    for (int mi = 0; mi < 4; mi++)
#pragma unroll
        for (int nf = 0; nf < 8; nf++) {
            int col = wn * 64 + nf * 8 + (lane & 3) * 2;
#pragma unroll
            for (int rg = 0; rg < 2; rg++) {
                int row = wm * 64 + mi * 16 + rg * 8 + (lane >> 2);
                float vx = acc[mi][nf][rg * 2], vy = acc[mi][nf][rg * 2 + 1];
                __nv_bfloat16 hx = __float2bfloat16_rn(vx);
                __nv_bfloat16 hy = __float2bfloat16_rn(vy);
                float lx = vx - __bfloat162float(hx);
                float ly = vy - __bfloat162float(hy);
                size_t so = ((size_t)row * T_STR + col) * 2;
                __nv_bfloat162 hp; hp.x = hx; hp.y = hy;
                *(uint32_t*)(sm + OFF_TH + so) = reinterpret_cast<uint32_t&>(hp);
                *(uint32_t*)(sm + OFF_TL + so) = pkbf2(lx, ly);
                acc[mi][nf][rg * 2] = 0.0f;
                acc[mi][nf][rg * 2 + 1] = 0.0f;
            }
        }
    __syncthreads();

    // ---------------- pass 2: out = T * M^T ----------------
#pragma unroll 1
    for (int kc = 0; kc < 8; kc++) {
        {   // B tile: all 256 M rows (n), cols [kc*32, +32)
            size_t go = (size_t)t * N + kc * 32;
            const uint4* ph = (const uint4*)(Mh + go);
            const uint4* pl = (const uint4*)(Ml + go);
#pragma unroll
            for (int j = 0; j < 4; j++) {
                size_t so = ((size_t)t * A_STR + j * 8) * 2;
                *(uint4*)(sm + OFF_BH + so) = ph[j];
                *(uint4*)(sm + OFF_BL + so) = pl[j];
            }
        }
        __syncthreads();
#pragma unroll
        for (int ks = 0; ks < 2; ks++) {
            uint32_t Ah[4][4], Al[4][4], Bh[4][4], Bl[4][4];
#pragma unroll
            for (int mi = 0; mi < 4; mi++) {
                uint32_t a = sb + OFF_TH +
                             ((wm * 64 + mi * 16 + lr) * T_STR + kc * 32 + ks * 16 + lc8) * 2;
                ldsm4(Ah[mi], a);
                ldsm4(Al[mi], a + SZ_T);
            }
#pragma unroll
            for (int nj = 0; nj < 4; nj++) {
                uint32_t a = sb + OFF_BH + ((wn * 64 + nj * 16 + lr) * A_STR + ks * 16 + lc8) * 2;
                ldsm4(Bh[nj], a);
                ldsm4(Bl[nj], a + SZ_B);
            }
            // non-trans B pairing: frag n0-7 = {r0, r2}, n8-15 = {r1, r3}
#pragma unroll
            for (int mi = 0; mi < 4; mi++)
#pragma unroll
                for (int nj = 0; nj < 4; nj++) {
                    mma_bf16(acc[mi][nj * 2],     Ah[mi], Bh[nj][0], Bh[nj][2]);
                    mma_bf16(acc[mi][nj * 2 + 1], Ah[mi], Bh[nj][1], Bh[nj][3]);
                    mma_bf16(acc[mi][nj * 2],     Ah[mi], Bl[nj][0], Bl[nj][2]);
                    mma_bf16(acc[mi][nj * 2 + 1], Ah[mi], Bl[nj][1], Bl[nj][3]);
                    mma_bf16(acc[mi][nj * 2],     Al[mi], Bh[nj][0], Bh[nj][2]);
                    mma_bf16(acc[mi][nj * 2 + 1], Al[mi], Bh[nj][1], Bh[nj][3]);
                }
        }
        __syncthreads();
    }

    // epilogue: fp32 store
    float* O = Out + ((size_t)z * N + h * 128) * N;
#pragma unroll
    for (int mi = 0; mi < 4; mi++)
#pragma unroll
        for (int nf = 0; nf < 8; nf++) {
            int col = wn * 64 + nf * 8 + (lane & 3) * 2;
#pragma unroll
            for (int rg = 0; rg < 2; rg++) {
                int row = wm * 64 + mi * 16 + rg * 8 + (lane >> 2);
                float2 v = make_float2(acc[mi][nf][rg * 2], acc[mi][nf][rg * 2 + 1]);
                *(float2*)&O[(size_t)row * N + col] = v;
            }
        }
}

// ---------------- host ----------------
extern "C" void kernel_launch(void* const* d_in, const int* in_sizes, int n_in,
                              void* d_out, int out_size) {
    const float* x = nullptr;
    const float* sigmas = nullptr;
    const int* steps = nullptr;
    for (int i = 0; i < n_in; i++) {
        if (in_sizes[i] == NSTEPS)      sigmas = (const float*)d_in[i];
        else if (in_sizes[i] == 128)    steps  = (const int*)d_in[i];
        else                            x      = (const float*)d_in[i];
    }
    float* out = (float*)d_out;

    cudaFuncSetAttribute(k_fused, cudaFuncAttributeMaxDynamicSharedMemorySize, SMEM_FUSED);

    k_init<<<N, N>>>(sigmas);
    k_gemm0<<<dim3(N / BN, N / BM, NSTEPS), 256>>>();
    k_split_M<<<NSTEPS, 256>>>();
    k_fused<<<dim3(NIMG, 2), 256, SMEM_FUSED>>>(x, out, steps);
}

// round 5
// speedup vs baseline: 2.0573x; 1.2575x over previous
#include <cuda_runtime.h>
#include <cuda_bf16.h>
#include <math.h>
#include <stdint.h>

namespace {
constexpr int N      = 256;
constexpr int NSTEPS = 32;
constexpr int NIMG   = 384;                  // 128 batch * 3 channels

// fp32 M-builder tile
constexpr int BM = 128, BN = 128, BK = 16;
constexpr int LDSW = BM + 4;

// k_mm smem: double-buffered stages
// A: 128 rows x 40 elems (80B rows)   -> 10240 B per matrix
// B: mode1 32 x 136 (272B rows), mode2 128 x 40 -> <= 10240 B per matrix
constexpr int OFF_AH = 0;
constexpr int OFF_AL = 10240;
constexpr int OFF_BH = 20480;
constexpr int OFF_BL = 30720;
constexpr int BUFSZ  = 40960;
constexpr int SMEM_MM = 2 * BUFSZ;           // 81920
}

// ---------------- device globals ----------------
__device__ float g_D[N * N];
__device__ float g_E[NSTEPS * N];
__device__ float g_M[NSTEPS * N * N];
__device__ __align__(16) __nv_bfloat16 g_Mh[NSTEPS * N * N];
__device__ __align__(16) __nv_bfloat16 g_Ml[NSTEPS * N * N];
__device__ __align__(16) __nv_bfloat16 g_Xh[NIMG * N * N];
__device__ __align__(16) __nv_bfloat16 g_Xl[NIMG * N * N];
__device__ __align__(16) __nv_bfloat16 g_Th[NIMG * N * N];
__device__ __align__(16) __nv_bfloat16 g_Tl[NIMG * N * N];

// ---------------- helpers ----------------
__device__ __forceinline__ uint32_t smem_u32(const void* p) {
    uint32_t a;
    asm("{ .reg .u64 t; cvta.to.shared.u64 t, %1; cvt.u32.u64 %0, t; }" : "=r"(a) : "l"(p));
    return a;
}
__device__ __forceinline__ void cp16(uint32_t s, const void* g) {
    asm volatile("cp.async.cg.shared.global [%0], [%1], 16;" :: "r"(s), "l"(g) : "memory");
}
__device__ __forceinline__ void cp_commit() {
    asm volatile("cp.async.commit_group;" ::: "memory");
}
__device__ __forceinline__ void cp_wait0() {
    asm volatile("cp.async.wait_group 0;" ::: "memory");
}
__device__ __forceinline__ void ldsm4(uint32_t* r, uint32_t a) {
    asm volatile("ldmatrix.sync.aligned.m8n8.x4.shared.b16 {%0,%1,%2,%3}, [%4];"
                 : "=r"(r[0]), "=r"(r[1]), "=r"(r[2]), "=r"(r[3]) : "r"(a));
}
__device__ __forceinline__ void ldsm4t(uint32_t* r, uint32_t a) {
    asm volatile("ldmatrix.sync.aligned.m8n8.x4.trans.shared.b16 {%0,%1,%2,%3}, [%4];"
                 : "=r"(r[0]), "=r"(r[1]), "=r"(r[2]), "=r"(r[3]) : "r"(a));
}
__device__ __forceinline__ void mma_bf16(float* d, const uint32_t* a, uint32_t b0, uint32_t b1) {
    asm volatile(
        "mma.sync.aligned.m16n8k16.row.col.f32.bf16.bf16.f32 "
        "{%0,%1,%2,%3}, {%4,%5,%6,%7}, {%8,%9}, {%0,%1,%2,%3};"
        : "+f"(d[0]), "+f"(d[1]), "+f"(d[2]), "+f"(d[3])
        : "r"(a[0]), "r"(a[1]), "r"(a[2]), "r"(a[3]), "r"(b0), "r"(b1));
}
__device__ __forceinline__ uint32_t pkbf2(float a, float b) {
    __nv_bfloat162 t = __floats2bfloat162_rn(a, b);
    return reinterpret_cast<uint32_t&>(t);
}
__device__ __forceinline__ void split8(const float* v, uint4& H, uint4& L) {
    float h[8], l[8];
#pragma unroll
    for (int i = 0; i < 8; i++) {
        __nv_bfloat16 b = __float2bfloat16_rn(v[i]);
        h[i] = __bfloat162float(b);
        l[i] = v[i] - h[i];
    }
    H = make_uint4(pkbf2(h[0], h[1]), pkbf2(h[2], h[3]), pkbf2(h[4], h[5]), pkbf2(h[6], h[7]));
    L = make_uint4(pkbf2(l[0], l[1]), pkbf2(l[2], l[3]), pkbf2(l[4], l[5]), pkbf2(l[6], l[7]));
}

// ---------------- init: D and E ----------------
__global__ void k_init(const float* __restrict__ sigmas) {
    int k = blockIdx.x, n = threadIdx.x;
    int p = ((2 * n + 1) * k) & (4 * N - 1);
    double v = sqrt(2.0 / (double)N) * cos(M_PI * (double)p / (double)(2 * N));
    if (k == 0) v *= 0.7071067811865476;
    g_D[k * N + n] = (float)v;
    if (k < NSTEPS) {
        float sig = sigmas[k];
        float t = 0.5f * sig * sig;
        float f = (float)M_PI * (float)n / (float)N;
        g_E[k * N + n] = expf(-f * f * t);
    }
}

// ---------------- fp32 builder: M_s = (D diag(e)) D ----------------
typedef unsigned long long u64;
__device__ __forceinline__ u64 pack2(float x, float y) {
    u64 r; asm("mov.b64 %0, {%1, %2};" : "=l"(r) : "f"(x), "f"(y)); return r;
}
__device__ __forceinline__ void unpack2(u64 v, float& x, float& y) {
    asm("mov.b64 {%0, %1}, %2;" : "=f"(x), "=f"(y) : "l"(v));
}
__device__ __forceinline__ void ffma2(u64& d, u64 a, u64 b) {
    asm("fma.rn.f32x2 %0, %1, %2, %0;" : "+l"(d) : "l"(a), "l"(b));
}

__global__ __launch_bounds__(256, 2) void k_gemm0() {
    __shared__ float As[BK][LDSW];
    __shared__ float Bs[BK][LDSW];
    const int z = blockIdx.z;
    const float* A = g_D;
    const float* B = g_D;
    float* C = g_M + (size_t)z * N * N;
    const float* e = g_E + z * N;

    const int m0 = blockIdx.y * BM, n0 = blockIdx.x * BN;
    const int tid = threadIdx.x;
    const int ty = tid >> 4, tx = tid & 15;
    const int lr = (tid * 2) >> 2, lc = (tid * 2) & 3;
    const int bkr = (tid * 2) >> 5, bnc = (tid * 2) & 31;

    u64 acc[8][4];
#pragma unroll
    for (int i = 0; i < 8; i++)
#pragma unroll
        for (int j = 0; j < 4; j++) acc[i][j] = 0ull;

    for (int k0 = 0; k0 < N; k0 += BK) {
        float4 a0 = *(const float4*)&A[(size_t)(m0 + lr) * N + k0 + lc * 4];
        float4 a1 = *(const float4*)&A[(size_t)(m0 + lr) * N + k0 + lc * 4 + 4];
        a0.x *= e[k0 + lc * 4 + 0]; a0.y *= e[k0 + lc * 4 + 1];
        a0.z *= e[k0 + lc * 4 + 2]; a0.w *= e[k0 + lc * 4 + 3];
        a1.x *= e[k0 + lc * 4 + 4]; a1.y *= e[k0 + lc * 4 + 5];
        a1.z *= e[k0 + lc * 4 + 6]; a1.w *= e[k0 + lc * 4 + 7];
        float4 b0 = *(const float4*)&B[(size_t)(k0 + bkr) * N + n0 + bnc * 4];
        float4 b1 = *(const float4*)&B[(size_t)(k0 + bkr) * N + n0 + bnc * 4 + 4];
        __syncthreads();
        As[lc * 4 + 0][lr] = a0.x; As[lc * 4 + 1][lr] = a0.y;
        As[lc * 4 + 2][lr] = a0.z; As[lc * 4 + 3][lr] = a0.w;
        As[lc * 4 + 4][lr] = a1.x; As[lc * 4 + 5][lr] = a1.y;
        As[lc * 4 + 6][lr] = a1.z; As[lc * 4 + 7][lr] = a1.w;
        *(float4*)&Bs[bkr][bnc * 4]     = b0;
        *(float4*)&Bs[bkr][bnc * 4 + 4] = b1;
        __syncthreads();
#pragma unroll
        for (int kk = 0; kk < BK; kk++) {
            float4 av0 = *(const float4*)&As[kk][ty * 4];
            float4 av1 = *(const float4*)&As[kk][64 + ty * 4];
            float4 bv0 = *(const float4*)&Bs[kk][tx * 4];
            float4 bv1 = *(const float4*)&Bs[kk][64 + tx * 4];
            u64 a2[8] = {pack2(av0.x, av0.x), pack2(av0.y, av0.y), pack2(av0.z, av0.z),
                         pack2(av0.w, av0.w), pack2(av1.x, av1.x), pack2(av1.y, av1.y),
                         pack2(av1.z, av1.z), pack2(av1.w, av1.w)};
            u64 b2[4] = {pack2(bv0.x, bv0.y), pack2(bv0.z, bv0.w),
                         pack2(bv1.x, bv1.y), pack2(bv1.z, bv1.w)};
#pragma unroll
            for (int i = 0; i < 8; i++)
#pragma unroll
                for (int j = 0; j < 4; j++) ffma2(acc[i][j], a2[i], b2[j]);
        }
    }
#pragma unroll
    for (int i = 0; i < 8; i++) {
        const int row = m0 + ((i < 4) ? (ty * 4 + i) : (64 + ty * 4 + (i - 4)));
        float4 c0, c1;
        unpack2(acc[i][0], c0.x, c0.y); unpack2(acc[i][1], c0.z, c0.w);
        unpack2(acc[i][2], c1.x, c1.y); unpack2(acc[i][3], c1.z, c1.w);
        *(float4*)&C[(size_t)row * N + n0 + tx * 4]      = c0;
        *(float4*)&C[(size_t)row * N + n0 + 64 + tx * 4] = c1;
    }
}

// ---------------- split fp32 matrix into bf16 hi/lo (row-major) ----------------
__global__ void k_split(const float* __restrict__ src0,
                        __nv_bfloat16* __restrict__ dh0,
                        __nv_bfloat16* __restrict__ dl0) {
    const size_t base0 = (size_t)blockIdx.x * N * N;
    const float* src = src0 + base0;
    __nv_bfloat16* dh = dh0 + base0;
    __nv_bfloat16* dl = dl0 + base0;
#pragma unroll 1
    for (int it = 0; it < 32; it++) {
        int base = it * 2048 + threadIdx.x * 8;
        float4 v0 = *(const float4*)&src[base];
        float4 v1 = *(const float4*)&src[base + 4];
        float v[8] = {v0.x, v0.y, v0.z, v0.w, v1.x, v1.y, v1.z, v1.w};
        uint4 H, L; split8(v, H, L);
        *(uint4*)&dh[base] = H;
        *(uint4*)&dl[base] = L;
    }
}

// ---------------- MMA kernel ----------------
// grid (NIMG, 2, 2) = (z, h, nh); 256 threads; warp grid 4m x 2n; warp tile 32x64.
// MODE 1: T[z](h*128.., nh*128..) = M[s](h rows) * X[z]          (B trans)
// MODE 2: out[z](h*128.., nh*128..) = T[z](h rows) * M[s]^T      (B non-trans)
template <int MODE>
__global__ __launch_bounds__(256, 2) void k_mm(float* __restrict__ Out,
                                               const int* __restrict__ steps) {
    extern __shared__ char sm[];
    const int z = blockIdx.x, h = blockIdx.y, nh = blockIdx.z;
    const int s = steps[z / 3];
    const int t = threadIdx.x, lane = t & 31, wid = t >> 5;
    const int wm = wid >> 1, wn = wid & 1;
    const uint32_t sb = smem_u32(sm);
    const int lr = lane & 15, lc8 = (lane >> 4) * 8;

    const char* Ah_g;
    const char* Al_g;
    const char* Bh_g;
    const char* Bl_g;
    if (MODE == 1) {
        Ah_g = (const char*)(g_Mh + (size_t)s * N * N);
        Al_g = (const char*)(g_Ml + (size_t)s * N * N);
        Bh_g = (const char*)(g_Xh + (size_t)z * N * N);
        Bl_g = (const char*)(g_Xl + (size_t)z * N * N);
    } else {
        Ah_g = (const char*)(g_Th + (size_t)z * N * N);
        Al_g = (const char*)(g_Tl + (size_t)z * N * N);
        Bh_g = (const char*)(g_Mh + (size_t)s * N * N);
        Bl_g = (const char*)(g_Ml + (size_t)s * N * N);
    }

    // stage loader for K-chunk kc into buffer b
    auto stage = [&](int kc, int b) {
        const uint32_t bo = sb + b * BUFSZ;
#pragma unroll
        for (int i = 0; i < 2; i++) {
            int c = t + i * 256;
            {   // A: 128 rows x 64B (hi) ; row-major stride 512B, tile col off kc*64B
                int r = c >> 2, q = c & 3;
                size_t go = (size_t)(h * 128 + r) * 512 + kc * 64 + q * 16;
                cp16(bo + OFF_AH + r * 80 + q * 16, Ah_g + go);
                cp16(bo + OFF_AL + r * 80 + q * 16, Al_g + go);
            }
            if (MODE == 1) {  // B: X rows kc*32.. x cols nh*128.. (32 x 256B)
                int r = c >> 4, q = c & 15;
                size_t go = (size_t)(kc * 32 + r) * 512 + nh * 256 + q * 16;
                cp16(bo + OFF_BH + r * 272 + q * 16, Bh_g + go);
                cp16(bo + OFF_BL + r * 272 + q * 16, Bl_g + go);
            } else {          // B: M rows nh*128.. x cols kc*32.. (128 x 64B)
                int r = c >> 2, q = c & 3;
                size_t go = (size_t)(nh * 128 + r) * 512 + kc * 64 + q * 16;
                cp16(bo + OFF_BH + r * 80 + q * 16, Bh_g + go);
                cp16(bo + OFF_BL + r * 80 + q * 16, Bl_g + go);
            }
        }
        cp_commit();
    };

    float acc[2][8][4];
#pragma unroll
    for (int a = 0; a < 2; a++)
#pragma unroll
        for (int b = 0; b < 8; b++)
#pragma unroll
            for (int c = 0; c < 4; c++) acc[a][b][c] = 0.0f;

    stage(0, 0);

#pragma unroll 1
    for (int kc = 0; kc < 8; kc++) {
        cp_wait0();
        __syncthreads();
        if (kc < 7) stage(kc + 1, (kc + 1) & 1);
        const uint32_t bo = sb + (kc & 1) * BUFSZ;

#pragma unroll
        for (int ks = 0; ks < 2; ks++) {
            uint32_t Af[2][4], Al2[2][4], Bf[4][4];
#pragma unroll
            for (int mi = 0; mi < 2; mi++) {
                uint32_t a = bo + OFF_AH + ((wm * 32 + mi * 16 + lr) * 40 + ks * 16 + lc8) * 2;
                ldsm4(Af[mi], a);
                ldsm4(Al2[mi], a + (OFF_AL - OFF_AH));
            }
            // --- B hi ---
#pragma unroll
            for (int nj = 0; nj < 4; nj++) {
                if (MODE == 1) {
                    uint32_t a = bo + OFF_BH + ((ks * 16 + lr) * 136 + wn * 64 + nj * 16 + lc8) * 2;
                    ldsm4t(Bf[nj], a);
                } else {
                    uint32_t a = bo + OFF_BH + ((wn * 64 + nj * 16 + lr) * 40 + ks * 16 + lc8) * 2;
                    ldsm4(Bf[nj], a);
                }
            }
#pragma unroll
            for (int mi = 0; mi < 2; mi++)
#pragma unroll
                for (int nj = 0; nj < 4; nj++) {
                    const int p0 = (MODE == 1) ? 0 : 0, p1 = (MODE == 1) ? 1 : 2;
                    const int p2 = (MODE == 1) ? 2 : 1, p3 = (MODE == 1) ? 3 : 3;
                    mma_bf16(acc[mi][nj * 2],     Af[mi],  Bf[nj][p0], Bf[nj][p1]);
                    mma_bf16(acc[mi][nj * 2 + 1], Af[mi],  Bf[nj][p2], Bf[nj][p3]);
                    mma_bf16(acc[mi][nj * 2],     Al2[mi], Bf[nj][p0], Bf[nj][p1]);
                    mma_bf16(acc[mi][nj * 2 + 1], Al2[mi], Bf[nj][p2], Bf[nj][p3]);
                }
            // --- B lo ---
#pragma unroll
            for (int nj = 0; nj < 4; nj++) {
                if (MODE == 1) {
                    uint32_t a = bo + OFF_BL + ((ks * 16 + lr) * 136 + wn * 64 + nj * 16 + lc8) * 2;
                    ldsm4t(Bf[nj], a);
                } else {
                    uint32_t a = bo + OFF_BL + ((wn * 64 + nj * 16 + lr) * 40 + ks * 16 + lc8) * 2;
                    ldsm4(Bf[nj], a);
                }
            }
#pragma unroll
            for (int mi = 0; mi < 2; mi++)
#pragma unroll
                for (int nj = 0; nj < 4; nj++) {
                    const int p0 = (MODE == 1) ? 0 : 0, p1 = (MODE == 1) ? 1 : 2;
                    const int p2 = (MODE == 1) ? 2 : 1, p3 = (MODE == 1) ? 3 : 3;
                    mma_bf16(acc[mi][nj * 2],     Af[mi], Bf[nj][p0], Bf[nj][p1]);
                    mma_bf16(acc[mi][nj * 2 + 1], Af[mi], Bf[nj][p2], Bf[nj][p3]);
                }
        }
        __syncthreads();
    }

    // epilogue
#pragma unroll
    for (int mi = 0; mi < 2; mi++)
#pragma unroll
        for (int nf = 0; nf < 8; nf++) {
            int col = nh * 128 + wn * 64 + nf * 8 + (lane & 3) * 2;
#pragma unroll
            for (int rg = 0; rg < 2; rg++) {
                int row = h * 128 + wm * 32 + mi * 16 + rg * 8 + (lane >> 2);
                float vx = acc[mi][nf][rg * 2], vy = acc[mi][nf][rg * 2 + 1];
                if (MODE == 1) {
                    __nv_bfloat16 hx = __float2bfloat16_rn(vx);
                    __nv_bfloat16 hy = __float2bfloat16_rn(vy);
                    float lx = vx - __bfloat162float(hx);
                    float ly = vy - __bfloat162float(hy);
                    __nv_bfloat162 hp; hp.x = hx; hp.y = hy;
                    size_t go = (size_t)z * N * N + (size_t)row * N + col;
                    *(uint32_t*)&g_Th[go] = reinterpret_cast<uint32_t&>(hp);
                    *(uint32_t*)&g_Tl[go] = pkbf2(lx, ly);
                } else {
                    *(float2*)&Out[(size_t)z * N * N + (size_t)row * N + col] =
                        make_float2(vx, vy);
                }
            }
        }
}

// ---------------- host ----------------
extern "C" void kernel_launch(void* const* d_in, const int* in_sizes, int n_in,
                              void* d_out, int out_size) {
    const float* x = nullptr;
    const float* sigmas = nullptr;
    const int* steps = nullptr;
    for (int i = 0; i < n_in; i++) {
        if (in_sizes[i] == NSTEPS)      sigmas = (const float*)d_in[i];
        else if (in_sizes[i] == 128)    steps  = (const int*)d_in[i];
        else                            x      = (const float*)d_in[i];
    }
    float* out = (float*)d_out;

    cudaFuncSetAttribute(k_mm<1>, cudaFuncAttributeMaxDynamicSharedMemorySize, SMEM_MM);
    cudaFuncSetAttribute(k_mm<2>, cudaFuncAttributeMaxDynamicSharedMemorySize, SMEM_MM);

    __nv_bfloat16 *mh, *ml, *xh, *xl;
    float* m;
    cudaGetSymbolAddress((void**)&m,  g_M);
    cudaGetSymbolAddress((void**)&mh, g_Mh);
    cudaGetSymbolAddress((void**)&ml, g_Ml);
    cudaGetSymbolAddress((void**)&xh, g_Xh);
    cudaGetSymbolAddress((void**)&xl, g_Xl);

    k_init<<<N, N>>>(sigmas);
    k_gemm0<<<dim3(N / BN, N / BM, NSTEPS), 256>>>();
    k_split<<<NSTEPS, 256>>>(m, mh, ml);
    k_split<<<NIMG, 256>>>(x, xh, xl);
    k_mm<1><<<dim3(NIMG, 2, 2), 256, SMEM_MM>>>(nullptr, steps);
    k_mm<2><<<dim3(NIMG, 2, 2), 256, SMEM_MM>>>(out, steps);
}

// round 6
// speedup vs baseline: 2.2277x; 1.0828x over previous
#include <cuda_runtime.h>
#include <cuda_bf16.h>
#include <math.h>
#include <stdint.h>

namespace {
constexpr int N      = 256;
constexpr int NSTEPS = 32;
constexpr int NIMG   = 384;                  // 128 batch * 3 channels

// fp32 M-builder tile
constexpr int BM = 128, BN = 128, BK = 16;
constexpr int LDSW = BM + 4;

// ---- k_mm smem maps (bytes) ----
// MODE 1: per double-buffer: A hi 10240 | A lo 10240 | B fp32 stage 16896  = 37376
//         single convert dest: B hi 8704 | B lo 8704 at 2*BUFSZ
constexpr int M1_AH   = 0;
constexpr int M1_AL   = 10240;
constexpr int M1_BS   = 20480;
constexpr int M1_BUF  = 37376;
constexpr int M1_CBH  = 2 * M1_BUF;          // 74752
constexpr int M1_CBL  = M1_CBH + 8704;
constexpr int M1_SMEM = M1_CBL + 8704;       // 92160
// MODE 2: per double-buffer: A fp32 stage 18432 | B hi 10240 | B lo 10240 = 38912
//         single convert dest: A hi 10240 | A lo 10240 at 2*BUFSZ
constexpr int M2_AS   = 0;
constexpr int M2_BH   = 18432;
constexpr int M2_BL   = 28672;
constexpr int M2_BUF  = 38912;
constexpr int M2_CAH  = 2 * M2_BUF;          // 77824
constexpr int M2_CAL  = M2_CAH + 10240;
constexpr int M2_SMEM = M2_CAL + 10240;      // 98304
}

// ---------------- device globals ----------------
__device__ float g_D[N * N];
__device__ float g_E[NSTEPS * N];
__device__ float g_M[NSTEPS * N * N];
__device__ __align__(16) __nv_bfloat16 g_Mh[NSTEPS * N * N];
__device__ __align__(16) __nv_bfloat16 g_Ml[NSTEPS * N * N];
__device__ __align__(16) float g_T[NIMG * N * N];     // fp32 intermediate

// ---------------- helpers ----------------
__device__ __forceinline__ uint32_t smem_u32(const void* p) {
    uint32_t a;
    asm("{ .reg .u64 t; cvta.to.shared.u64 t, %1; cvt.u32.u64 %0, t; }" : "=r"(a) : "l"(p));
    return a;
}
__device__ __forceinline__ void cp16(uint32_t s, const void* g) {
    asm volatile("cp.async.cg.shared.global [%0], [%1], 16;" :: "r"(s), "l"(g) : "memory");
}
__device__ __forceinline__ void cp_commit() {
    asm volatile("cp.async.commit_group;" ::: "memory");
}
__device__ __forceinline__ void cp_wait0() {
    asm volatile("cp.async.wait_group 0;" ::: "memory");
}
__device__ __forceinline__ void ldsm4(uint32_t* r, uint32_t a) {
    asm volatile("ldmatrix.sync.aligned.m8n8.x4.shared.b16 {%0,%1,%2,%3}, [%4];"
                 : "=r"(r[0]), "=r"(r[1]), "=r"(r[2]), "=r"(r[3]) : "r"(a));
}
__device__ __forceinline__ void ldsm4t(uint32_t* r, uint32_t a) {
    asm volatile("ldmatrix.sync.aligned.m8n8.x4.trans.shared.b16 {%0,%1,%2,%3}, [%4];"
                 : "=r"(r[0]), "=r"(r[1]), "=r"(r[2]), "=r"(r[3]) : "r"(a));
}
__device__ __forceinline__ void mma_bf16(float* d, const uint32_t* a, uint32_t b0, uint32_t b1) {
    asm volatile(
        "mma.sync.aligned.m16n8k16.row.col.f32.bf16.bf16.f32 "
        "{%0,%1,%2,%3}, {%4,%5,%6,%7}, {%8,%9}, {%0,%1,%2,%3};"
        : "+f"(d[0]), "+f"(d[1]), "+f"(d[2]), "+f"(d[3])
        : "r"(a[0]), "r"(a[1]), "r"(a[2]), "r"(a[3]), "r"(b0), "r"(b1));
}
__device__ __forceinline__ uint32_t pkbf2(float a, float b) {
    __nv_bfloat162 t = __floats2bfloat162_rn(a, b);
    return reinterpret_cast<uint32_t&>(t);
}
__device__ __forceinline__ void split8(const float* v, uint4& H, uint4& L) {
    float h[8], l[8];
#pragma unroll
    for (int i = 0; i < 8; i++) {
        __nv_bfloat16 b = __float2bfloat16_rn(v[i]);
        h[i] = __bfloat162float(b);
        l[i] = v[i] - h[i];
    }
    H = make_uint4(pkbf2(h[0], h[1]), pkbf2(h[2], h[3]), pkbf2(h[4], h[5]), pkbf2(h[6], h[7]));
    L = make_uint4(pkbf2(l[0], l[1]), pkbf2(l[2], l[3]), pkbf2(l[4], l[5]), pkbf2(l[6], l[7]));
}

// ---------------- init: D and E ----------------
__global__ void k_init(const float* __restrict__ sigmas) {
    int k = blockIdx.x, n = threadIdx.x;
    int p = ((2 * n + 1) * k) & (4 * N - 1);
    double v = sqrt(2.0 / (double)N) * cos(M_PI * (double)p / (double)(2 * N));
    if (k == 0) v *= 0.7071067811865476;
    g_D[k * N + n] = (float)v;
    if (k < NSTEPS) {
        float sig = sigmas[k];
        float t = 0.5f * sig * sig;
        float f = (float)M_PI * (float)n / (float)N;
        g_E[k * N + n] = expf(-f * f * t);
    }
}

// ---------------- fp32 builder: M_s = (D diag(e)) D ----------------
typedef unsigned long long u64;
__device__ __forceinline__ u64 pack2(float x, float y) {
    u64 r; asm("mov.b64 %0, {%1, %2};" : "=l"(r) : "f"(x), "f"(y)); return r;
}
__device__ __forceinline__ void unpack2(u64 v, float& x, float& y) {
    asm("mov.b64 {%0, %1}, %2;" : "=f"(x), "=f"(y) : "l"(v));
}
__device__ __forceinline__ void ffma2(u64& d, u64 a, u64 b) {
    asm("fma.rn.f32x2 %0, %1, %2, %0;" : "+l"(d) : "l"(a), "l"(b));
}

__global__ __launch_bounds__(256, 2) void k_gemm0() {
    __shared__ float As[BK][LDSW];
    __shared__ float Bs[BK][LDSW];
    const int z = blockIdx.z;
    const float* A = g_D;
    const float* B = g_D;
    float* C = g_M + (size_t)z * N * N;
    const float* e = g_E + z * N;

    const int m0 = blockIdx.y * BM, n0 = blockIdx.x * BN;
    const int tid = threadIdx.x;
    const int ty = tid >> 4, tx = tid & 15;
    const int lr = (tid * 2) >> 2, lc = (tid * 2) & 3;
    const int bkr = (tid * 2) >> 5, bnc = (tid * 2) & 31;

    u64 acc[8][4];
#pragma unroll
    for (int i = 0; i < 8; i++)
#pragma unroll
        for (int j = 0; j < 4; j++) acc[i][j] = 0ull;

    for (int k0 = 0; k0 < N; k0 += BK) {
        float4 a0 = *(const float4*)&A[(size_t)(m0 + lr) * N + k0 + lc * 4];
        float4 a1 = *(const float4*)&A[(size_t)(m0 + lr) * N + k0 + lc * 4 + 4];
        a0.x *= e[k0 + lc * 4 + 0]; a0.y *= e[k0 + lc * 4 + 1];
        a0.z *= e[k0 + lc * 4 + 2]; a0.w *= e[k0 + lc * 4 + 3];
        a1.x *= e[k0 + lc * 4 + 4]; a1.y *= e[k0 + lc * 4 + 5];
        a1.z *= e[k0 + lc * 4 + 6]; a1.w *= e[k0 + lc * 4 + 7];
        float4 b0 = *(const float4*)&B[(size_t)(k0 + bkr) * N + n0 + bnc * 4];
        float4 b1 = *(const float4*)&B[(size_t)(k0 + bkr) * N + n0 + bnc * 4 + 4];
        __syncthreads();
        As[lc * 4 + 0][lr] = a0.x; As[lc * 4 + 1][lr] = a0.y;
        As[lc * 4 + 2][lr] = a0.z; As[lc * 4 + 3][lr] = a0.w;
        As[lc * 4 + 4][lr] = a1.x; As[lc * 4 + 5][lr] = a1.y;
        As[lc * 4 + 6][lr] = a1.z; As[lc * 4 + 7][lr] = a1.w;
        *(float4*)&Bs[bkr][bnc * 4]     = b0;
        *(float4*)&Bs[bkr][bnc * 4 + 4] = b1;
        __syncthreads();
#pragma unroll
        for (int kk = 0; kk < BK; kk++) {
            float4 av0 = *(const float4*)&As[kk][ty * 4];
            float4 av1 = *(const float4*)&As[kk][64 + ty * 4];
            float4 bv0 = *(const float4*)&Bs[kk][tx * 4];
            float4 bv1 = *(const float4*)&Bs[kk][64 + tx * 4];
            u64 a2[8] = {pack2(av0.x, av0.x), pack2(av0.y, av0.y), pack2(av0.z, av0.z),
                         pack2(av0.w, av0.w), pack2(av1.x, av1.x), pack2(av1.y, av1.y),
                         pack2(av1.z, av1.z), pack2(av1.w, av1.w)};
            u64 b2[4] = {pack2(bv0.x, bv0.y), pack2(bv0.z, bv0.w),
                         pack2(bv1.x, bv1.y), pack2(bv1.z, bv1.w)};
#pragma unroll
            for (int i = 0; i < 8; i++)
#pragma unroll
                for (int j = 0; j < 4; j++) ffma2(acc[i][j], a2[i], b2[j]);
        }
    }
#pragma unroll
    for (int i = 0; i < 8; i++) {
        const int row = m0 + ((i < 4) ? (ty * 4 + i) : (64 + ty * 4 + (i - 4)));
        float4 c0, c1;
        unpack2(acc[i][0], c0.x, c0.y); unpack2(acc[i][1], c0.z, c0.w);
        unpack2(acc[i][2], c1.x, c1.y); unpack2(acc[i][3], c1.z, c1.w);
        *(float4*)&C[(size_t)row * N + n0 + tx * 4]      = c0;
        *(float4*)&C[(size_t)row * N + n0 + 64 + tx * 4] = c1;
    }
}

// ---------------- split M (fp32 -> bf16 hi/lo, row-major) ----------------
__global__ void k_split_M() {
    const size_t base0 = (size_t)blockIdx.x * N * N;
    const float* src = g_M + base0;
    __nv_bfloat16* dh = g_Mh + base0;
    __nv_bfloat16* dl = g_Ml + base0;
#pragma unroll 1
    for (int it = 0; it < 32; it++) {
        int base = it * 2048 + threadIdx.x * 8;
        float4 v0 = *(const float4*)&src[base];
        float4 v1 = *(const float4*)&src[base + 4];
        float v[8] = {v0.x, v0.y, v0.z, v0.w, v1.x, v1.y, v1.z, v1.w};
        uint4 H, L; split8(v, H, L);
        *(uint4*)&dh[base] = H;
        *(uint4*)&dl[base] = L;
    }
}

// ---------------- MMA kernel ----------------
// grid (NIMG, 2, 2) = (z, h, nh); 256 threads; warp grid 4m x 2n; warp tile 32x64.
// MODE 1: T[z](h rows, nh cols) = M[s](h rows) * X[z]        (B = fp32 X, split in-kernel)
// MODE 2: out[z](h rows, nh cols) = T[z](h rows) * M[s]^T    (A = fp32 T, split in-kernel)
template <int MODE>
__global__ __launch_bounds__(256, 2) void k_mm(const float* __restrict__ Xf,
                                               float* __restrict__ Out,
                                               const int* __restrict__ steps) {
    extern __shared__ char sm[];
    const int z = blockIdx.x, h = blockIdx.y, nh = blockIdx.z;
    const int s = steps[z / 3];
    const int t = threadIdx.x, lane = t & 31, wid = t >> 5;
    const int wm = wid >> 1, wn = wid & 1;
    const uint32_t sb = smem_u32(sm);
    const int lr = lane & 15, lc8 = (lane >> 4) * 8;

    constexpr int BUFSZ = (MODE == 1) ? M1_BUF : M2_BUF;

    const char* Mh_g = (const char*)(g_Mh + (size_t)s * N * N);
    const char* Ml_g = (const char*)(g_Ml + (size_t)s * N * N);
    const char* F_g  = (MODE == 1)
                     ? (const char*)(Xf + (size_t)z * N * N)     // fp32 X
                     : (const char*)(g_T + (size_t)z * N * N);   // fp32 T

    auto stage = [&](int kc, int b) {
        const uint32_t bo = sb + b * BUFSZ;
        if (MODE == 1) {
            // A = M hi/lo direct: 128 rows x 64B, tile col offset kc*64
#pragma unroll
            for (int i = 0; i < 2; i++) {
                int c = t + i * 256, r = c >> 2, q = c & 3;
                size_t go = (size_t)(h * 128 + r) * 512 + kc * 64 + q * 16;
                cp16(bo + M1_AH + r * 80 + q * 16, Mh_g + go);
                cp16(bo + M1_AL + r * 80 + q * 16, Ml_g + go);
            }
            // B = X fp32: rows kc*32..+32, cols nh*128..+128 (512B per row slice)
#pragma unroll
            for (int i = 0; i < 4; i++) {
                int c = t + i * 256, r = c >> 5, q = c & 31;
                size_t go = (size_t)(kc * 32 + r) * 1024 + nh * 512 + q * 16;
                cp16(bo + M1_BS + r * 528 + q * 16, F_g + go);
            }
        } else {
            // A = T fp32: rows h*128..+128, cols kc*32..+32 (128B per row slice)
#pragma unroll
            for (int i = 0; i < 4; i++) {
                int c = t + i * 256, r = c >> 3, q = c & 7;
                size_t go = (size_t)(h * 128 + r) * 1024 + kc * 128 + q * 16;
                cp16(bo + M2_AS + r * 144 + q * 16, F_g + go);
            }
            // B = M hi/lo direct: rows nh*128..+128 x 64B, col offset kc*64
#pragma unroll
            for (int i = 0; i < 2; i++) {
                int c = t + i * 256, r = c >> 2, q = c & 3;
                size_t go = (size_t)(nh * 128 + r) * 512 + kc * 64 + q * 16;
                cp16(bo + M2_BH + r * 80 + q * 16, Mh_g + go);
                cp16(bo + M2_BL + r * 80 + q * 16, Ml_g + go);
            }
        }
        cp_commit();
    };

    float acc[2][8][4];
#pragma unroll
    for (int a = 0; a < 2; a++)
#pragma unroll
        for (int b = 0; b < 8; b++)
#pragma unroll
            for (int c = 0; c < 4; c++) acc[a][b][c] = 0.0f;

    stage(0, 0);

#pragma unroll 1
    for (int kc = 0; kc < 8; kc++) {
        cp_wait0();
        __syncthreads();
        if (kc < 7) stage(kc + 1, (kc + 1) & 1);
        const uint32_t bo = sb + (kc & 1) * BUFSZ;
        const char* bufc = sm + (kc & 1) * BUFSZ;

        // convert staged fp32 -> bf16 hi/lo (single-buffered dest)
        if (MODE == 1) {
            // 32 x 128 fp32, stride 132 -> dest stride 136
            int r = t >> 3, cs = (t & 7) * 16;
            const float* src = (const float*)(bufc + M1_BS) + r * 132 + cs;
            char* dh = sm + M1_CBH + (r * 136 + cs) * 2;
            char* dl = sm + M1_CBL + (r * 136 + cs) * 2;
#pragma unroll
            for (int g = 0; g < 2; g++) {
                float4 v0 = *(const float4*)&src[g * 8];
                float4 v1 = *(const float4*)&src[g * 8 + 4];
                float v[8] = {v0.x, v0.y, v0.z, v0.w, v1.x, v1.y, v1.z, v1.w};
                uint4 H, L; split8(v, H, L);
                *(uint4*)(dh + g * 16) = H;
                *(uint4*)(dl + g * 16) = L;
            }
        } else {
            // 128 x 32 fp32, stride 36 -> dest stride 40
            int r = t >> 1, cs = (t & 1) * 16;
            const float* src = (const float*)(bufc + M2_AS) + r * 36 + cs;
            char* dh = sm + M2_CAH + (r * 40 + cs) * 2;
            char* dl = sm + M2_CAL + (r * 40 + cs) * 2;
#pragma unroll
            for (int g = 0; g < 2; g++) {
                float4 v0 = *(const float4*)&src[g * 8];
                float4 v1 = *(const float4*)&src[g * 8 + 4];
                float v[8] = {v0.x, v0.y, v0.z, v0.w, v1.x, v1.y, v1.z, v1.w};
                uint4 H, L; split8(v, H, L);
                *(uint4*)(dh + g * 16) = H;
                *(uint4*)(dl + g * 16) = L;
            }
        }
        __syncthreads();

#pragma unroll
        for (int ks = 0; ks < 2; ks++) {
            uint32_t Ah[2][4], Al2[2][4], Bf[4][4];
#pragma unroll
            for (int mi = 0; mi < 2; mi++) {
                uint32_t a;
                if (MODE == 1)
                    a = bo + M1_AH + ((wm * 32 + mi * 16 + lr) * 40 + ks * 16 + lc8) * 2;
                else
                    a = sb + M2_CAH + ((wm * 32 + mi * 16 + lr) * 40 + ks * 16 + lc8) * 2;
                ldsm4(Ah[mi], a);
                ldsm4(Al2[mi], a + ((MODE == 1) ? (M1_AL - M1_AH) : (M2_CAL - M2_CAH)));
            }
            // --- B hi ---
#pragma unroll
            for (int nj = 0; nj < 4; nj++) {
                if (MODE == 1) {
                    uint32_t a = sb + M1_CBH + ((ks * 16 + lr) * 136 + wn * 64 + nj * 16 + lc8) * 2;
                    ldsm4t(Bf[nj], a);
                } else {
                    uint32_t a = bo + M2_BH + ((wn * 64 + nj * 16 + lr) * 40 + ks * 16 + lc8) * 2;
                    ldsm4(Bf[nj], a);
                }
            }
            {
                const int p0 = 0, p1 = (MODE == 1) ? 1 : 2;
                const int p2 = (MODE == 1) ? 2 : 1, p3 = 3;
#pragma unroll
                for (int mi = 0; mi < 2; mi++)
#pragma unroll
                    for (int nj = 0; nj < 4; nj++) {
                        mma_bf16(acc[mi][nj * 2],     Ah[mi],  Bf[nj][p0], Bf[nj][p1]);
                        mma_bf16(acc[mi][nj * 2 + 1], Ah[mi],  Bf[nj][p2], Bf[nj][p3]);
                        mma_bf16(acc[mi][nj * 2],     Al2[mi], Bf[nj][p0], Bf[nj][p1]);
                        mma_bf16(acc[mi][nj * 2 + 1], Al2[mi], Bf[nj][p2], Bf[nj][p3]);
                    }
            }
            // --- B lo ---
#pragma unroll
            for (int nj = 0; nj < 4; nj++) {
                if (MODE == 1) {
                    uint32_t a = sb + M1_CBL + ((ks * 16 + lr) * 136 + wn * 64 + nj * 16 + lc8) * 2;
                    ldsm4t(Bf[nj], a);
                } else {
                    uint32_t a = bo + M2_BL + ((wn * 64 + nj * 16 + lr) * 40 + ks * 16 + lc8) * 2;
                    ldsm4(Bf[nj], a);
                }
            }
            {
                const int p0 = 0, p1 = (MODE == 1) ? 1 : 2;
                const int p2 = (MODE == 1) ? 2 : 1, p3 = 3;
#pragma unroll
                for (int mi = 0; mi < 2; mi++)
#pragma unroll
                    for (int nj = 0; nj < 4; nj++) {
                        mma_bf16(acc[mi][nj * 2],     Ah[mi], Bf[nj][p0], Bf[nj][p1]);
                        mma_bf16(acc[mi][nj * 2 + 1], Ah[mi], Bf[nj][p2], Bf[nj][p3]);
                    }
            }
        }
        __syncthreads();
    }

    // epilogue: fp32 store (T or Out)
    float* dst = (MODE == 1) ? (g_T + (size_t)z * N * N) : (Out + (size_t)z * N * N);
#pragma unroll
    for (int mi = 0; mi < 2; mi++)
#pragma unroll
        for (int nf = 0; nf < 8; nf++) {
            int col = nh * 128 + wn * 64 + nf * 8 + (lane & 3) * 2;
#pragma unroll
            for (int rg = 0; rg < 2; rg++) {
                int row = h * 128 + wm * 32 + mi * 16 + rg * 8 + (lane >> 2);
                *(float2*)&dst[(size_t)row * N + col] =
                    make_float2(acc[mi][nf][rg * 2], acc[mi][nf][rg * 2 + 1]);
            }
        }
}

// ---------------- host ----------------
extern "C" void kernel_launch(void* const* d_in, const int* in_sizes, int n_in,
                              void* d_out, int out_size) {
    const float* x = nullptr;
    const float* sigmas = nullptr;
    const int* steps = nullptr;
    for (int i = 0; i < n_in; i++) {
        if (in_sizes[i] == NSTEPS)      sigmas = (const float*)d_in[i];
        else if (in_sizes[i] == 128)    steps  = (const int*)d_in[i];
        else                            x      = (const float*)d_in[i];
    }
    float* out = (float*)d_out;

    cudaFuncSetAttribute(k_mm<1>, cudaFuncAttributeMaxDynamicSharedMemorySize, M1_SMEM);
    cudaFuncSetAttribute(k_mm<2>, cudaFuncAttributeMaxDynamicSharedMemorySize, M2_SMEM);

    k_init<<<N, N>>>(sigmas);
    k_gemm0<<<dim3(N / BN, N / BM, NSTEPS), 256>>>();
    k_split_M<<<NSTEPS, 256>>>();
    k_mm<1><<<dim3(NIMG, 2, 2), 256, M1_SMEM>>>(x, nullptr, steps);
    k_mm<2><<<dim3(NIMG, 2, 2), 256, M2_SMEM>>>(nullptr, out, steps);
}